// round 14
// baseline (speedup 1.0000x reference)
#include <cuda_runtime.h>
#include <cstdint>
#include <cstddef>

// SeparableConv3D: x[8,3,32,256,256] fp32, depthwise K=5 cross-correlation
// along W, then H, then T, zero 'same' padding each stage.
//
// R11 pipeline + triple-buffered staging + 4-row batched phase C:
//   phase A: prefetch 2 x-rows into regs (item A: all; item B: threads 0-63),
//            commit via aligned STS.128 at iter end
//   phase B (lane=t, wg=w-quad): W-conv (4 aligned LDS.64) + H-conv ring,
//            store s into pair-interleaved sbufP[ii%3][row][p][t][2]
//   phase C (EVERY 2ND iter, all 256 threads; thread=(row r, pair, t-seg)):
//            T-conv over 8t x 2w = 16 outputs from 6 LDS.128 (1.5x amp),
//            rolling 3-quad consume; reads the 2 buffers written at ii-2, ii-1
//   ONE __syncthreads per 2 h-rows. Loop split warmup/steady(unroll 6)/tail
//   so all %3 / %2 buffer selects are compile-time.

#define NN 8
#define CC 3
#define TT 32
#define HH 256
#define WW 256
#define KK 5

#define WT 32                 // w outputs per block
#define HC 32                 // h rows per block -> grid = 24*8*8 = 1536
#define NIT ((HC + 4) / 2)    // 18 iterations of 2 rows
#define XSTRIDE 44            // x slab row stride (conflict-free)
#define PSTR 68               // sbufP per-pair stride (floats)
#define ROWSTR (16 * PSTR)    // sbufP per-row stride (floats) = 1088

__global__ void __launch_bounds__(256, 4)
sepconv3d_fused(const float* __restrict__ x,
                const float* __restrict__ w1,   // along W
                const float* __restrict__ w2,   // along H
                const float* __restrict__ w3,   // along T
                float* __restrict__ out)
{
    __shared__ float xbuf[2][2][TT * XSTRIDE];    // [buf][row]
    __shared__ float sbufP[3][2][ROWSTR];         // [buf][row][pair][t][2]

    const int tid  = threadIdx.x;
    const int lane = tid & 31;     // phase B: = t
    const int wg   = tid >> 5;     // phase B: w-quad

    const int bid = blockIdx.x;               // 0..1535
    const int nc  = bid >> 6;                  // n*3+c
    const int rem = bid & 63;
    const int wt  = rem >> 3;                   // 0..7
    const int hcb = rem & 7;                    // 0..7
    const int c   = nc % CC;

    const int w0 = wt * WT;
    const int h0 = hcb * HC;
    const size_t HW = (size_t)HH * WW;

    const float wW0 = w1[c*KK+0], wW1 = w1[c*KK+1], wW2 = w1[c*KK+2], wW3 = w1[c*KK+3], wW4 = w1[c*KK+4];
    const float wH0 = w2[c*KK+0], wH1 = w2[c*KK+1], wH2 = w2[c*KK+2], wH3 = w2[c*KK+3], wH4 = w2[c*KK+4];
    const float wT0 = w3[c*KK+0], wT1 = w3[c*KK+1], wT2 = w3[c*KK+2], wT3 = w3[c*KK+3], wT4 = w3[c*KK+4];

    const float* xb = x   + (size_t)nc * (TT * HW);
    float*       ob = out + (size_t)nc * (TT * HW);

    // ---- slab-load geometry: item A = tid (all), item B = threads 0-63 ----
    const int trA = tid / 10,  qA = tid - trA * 10;
    const bool hasB = (tid < 64);
    const int iB  = 256 + tid;
    const int trB = iB / 10,   qB = iB - trB * 10;
    const int gwA = w0 - 4 + 4 * qA;
    const int gwB = w0 - 4 + 4 * qB;
    const bool wvA = (gwA >= 0) && (gwA < WW);
    const bool wvB = hasB && (gwB >= 0) && (gwB < WW);
    const float* gA = xb + (size_t)trA * HW + (wvA ? gwA : 0);   // + h*WW
    const float* gB = xb + (size_t)trB * HW + (wvB ? gwB : 0);

    // smem commit addresses (aligned STS.128)
    float* const xsA00 = &xbuf[0][0][trA * XSTRIDE + 4 * qA];
    float* const xsA01 = &xbuf[0][1][trA * XSTRIDE + 4 * qA];
    float* const xsA10 = &xbuf[1][0][trA * XSTRIDE + 4 * qA];
    float* const xsA11 = &xbuf[1][1][trA * XSTRIDE + 4 * qA];
    float* const xsB00 = &xbuf[0][0][trB * XSTRIDE + 4 * qB];
    float* const xsB01 = &xbuf[0][1][trB * XSTRIDE + 4 * qB];
    float* const xsB10 = &xbuf[1][0][trB * XSTRIDE + 4 * qB];
    float* const xsB11 = &xbuf[1][1][trB * XSTRIDE + 4 * qB];

    // ---- phase C geometry: thread = (row r, pair p, t-seg) ----
    const int p   = tid & 15;          // w pair: w = w0 + 2p, 2p+1
    const int seg = (tid >> 4) & 3;    // 8t segment
    const int r   = tid >> 6;          // 0..3: r<2 -> older buf, r>=2 -> newer
    const int rowsel = r & 1;
    const int t0  = 8 * seg;
    const int pbase = p * PSTR;
    const int qoff0 = pbase + max(2 * t0 - 4, 0);           // masked if seg==0
    const int qoff1 = pbase + 2 * t0;
    const int qoff2 = pbase + 2 * t0 + 4;
    const int qoff3 = pbase + 2 * t0 + 8;
    const int qoff4 = pbase + 2 * t0 + 12;
    const int qoff5 = pbase + min(2 * t0 + 16, 2 * TT - 8); // masked if seg==3
    const float mlo = (seg == 0) ? 0.f : 1.f;
    const float mhi = (seg == 3) ? 0.f : 1.f;
    // phase C read bases per buffer (row chosen by rowsel)
    const float* const spP0 = sbufP[0][rowsel];
    const float* const spP1 = sbufP[1][rowsel];
    const float* const spP2 = sbufP[2][rowsel];
    // at iteration ii (even, >=4) this thread writes output row h0 + 2ii - 8 + r
    float* opc = ob + (size_t)t0 * HW + w0 + 2 * p
                    + (ptrdiff_t)(h0 + r - 8) * (ptrdiff_t)WW;

    // H-conv register ring: g1..g4 = W-conv of the last 4 input rows
    float4 g1 = {0,0,0,0}, g2 = {0,0,0,0}, g3 = {0,0,0,0}, g4 = {0,0,0,0};
    const int scolbase = 4 * wg;
    // phase-B store bases (row a; row b = +ROWSTR)
    float* const sbW0 = &sbufP[0][0][(2 * wg) * PSTR + 2 * lane];
    float* const sbW1 = &sbufP[1][0][(2 * wg) * PSTR + 2 * lane];
    float* const sbW2 = &sbufP[2][0][(2 * wg) * PSTR + 2 * lane];

    // ================= helper macros ==========================================
#define PREFETCH(II)                                                           \
    float4 pa0 = {0,0,0,0}, pa1 = {0,0,0,0}, pb0 = {0,0,0,0}, pb1 = {0,0,0,0}; \
    {                                                                          \
        const int ha = h0 + 2 * (II);                                          \
        const int hb = ha + 1;                                                 \
        if (wvA && ha < HH) pa0 = *reinterpret_cast<const float4*>(gA + (size_t)ha * WW); \
        if (wvA && hb < HH) pa1 = *reinterpret_cast<const float4*>(gA + (size_t)hb * WW); \
        if (wvB && ha < HH) pb0 = *reinterpret_cast<const float4*>(gB + (size_t)ha * WW); \
        if (wvB && hb < HH) pb1 = *reinterpret_cast<const float4*>(gB + (size_t)hb * WW); \
    }

#define WCONV_ROWS(CUR)                                                        \
    float4 r_a, r_b;                                                           \
    {                                                                          \
        const float* row0 = &xbuf[CUR][0][lane * XSTRIDE + scolbase + 2];      \
        float2 a0 = *reinterpret_cast<const float2*>(row0);                    \
        float2 a1 = *reinterpret_cast<const float2*>(row0 + 2);                \
        float2 a2 = *reinterpret_cast<const float2*>(row0 + 4);                \
        float2 a3 = *reinterpret_cast<const float2*>(row0 + 6);                \
        r_a.x = wW0*a0.x + wW1*a0.y + wW2*a1.x + wW3*a1.y + wW4*a2.x;          \
        r_a.y = wW0*a0.y + wW1*a1.x + wW2*a1.y + wW3*a2.x + wW4*a2.y;          \
        r_a.z = wW0*a1.x + wW1*a1.y + wW2*a2.x + wW3*a2.y + wW4*a3.x;          \
        r_a.w = wW0*a1.y + wW1*a2.x + wW2*a2.y + wW3*a3.x + wW4*a3.y;          \
        const float* row1 = &xbuf[CUR][1][lane * XSTRIDE + scolbase + 2];      \
        float2 b0 = *reinterpret_cast<const float2*>(row1);                    \
        float2 b1 = *reinterpret_cast<const float2*>(row1 + 2);                \
        float2 b2 = *reinterpret_cast<const float2*>(row1 + 4);                \
        float2 b3 = *reinterpret_cast<const float2*>(row1 + 6);                \
        r_b.x = wW0*b0.x + wW1*b0.y + wW2*b1.x + wW3*b1.y + wW4*b2.x;          \
        r_b.y = wW0*b0.y + wW1*b1.x + wW2*b1.y + wW3*b2.x + wW4*b2.y;          \
        r_b.z = wW0*b1.x + wW1*b1.y + wW2*b2.x + wW3*b2.y + wW4*b3.x;          \
        r_b.w = wW0*b1.y + wW1*b2.x + wW2*b2.y + wW3*b3.x + wW4*b3.y;          \
    }

#define STORE_S(SA)                                                            \
    {                                                                          \
        float* sa = (SA);                                                      \
        float* sb = (SA) + ROWSTR;                                             \
        float sax = wH0*g1.x + wH1*g2.x + wH2*g3.x + wH3*g4.x + wH4*r_a.x;     \
        float say = wH0*g1.y + wH1*g2.y + wH2*g3.y + wH3*g4.y + wH4*r_a.y;     \
        float saz = wH0*g1.z + wH1*g2.z + wH2*g3.z + wH3*g4.z + wH4*r_a.z;     \
        float saw = wH0*g1.w + wH1*g2.w + wH2*g3.w + wH3*g4.w + wH4*r_a.w;     \
        *reinterpret_cast<float2*>(sa)        = make_float2(sax, say);         \
        *reinterpret_cast<float2*>(sa + PSTR) = make_float2(saz, saw);         \
        float sbx = wH0*g2.x + wH1*g3.x + wH2*g4.x + wH3*r_a.x + wH4*r_b.x;    \
        float sby = wH0*g2.y + wH1*g3.y + wH2*g4.y + wH3*r_a.y + wH4*r_b.y;    \
        float sbz = wH0*g2.z + wH1*g3.z + wH2*g4.z + wH3*r_a.z + wH4*r_b.z;    \
        float sbw = wH0*g2.w + wH1*g3.w + wH2*g4.w + wH3*r_a.w + wH4*r_b.w;    \
        *reinterpret_cast<float2*>(sb)        = make_float2(sbx, sby);         \
        *reinterpret_cast<float2*>(sb + PSTR) = make_float2(sbz, sbw);         \
    }

#define RING_SHIFT() { g1 = g3; g2 = g4; g3 = r_a; g4 = r_b; }

#define COMMIT(CUR)                                                            \
    {                                                                          \
        *reinterpret_cast<float4*>((CUR) ? xsA00 : xsA10) = pa0;               \
        *reinterpret_cast<float4*>((CUR) ? xsA01 : xsA11) = pa1;               \
        if (hasB) {                                                            \
            *reinterpret_cast<float4*>((CUR) ? xsB00 : xsB10) = pb0;           \
            *reinterpret_cast<float4*>((CUR) ? xsB01 : xsB11) = pb1;           \
        }                                                                      \
    }

    // 16 outputs (8t x 2w) for one row, rolling 3-quad consume (R12-proven)
#define PHASE_C16(SPBASE)                                                      \
    {                                                                          \
        const float* sp = (SPBASE);                                            \
        float4 Qa = *reinterpret_cast<const float4*>(sp + qoff0);              \
        float4 Qb = *reinterpret_cast<const float4*>(sp + qoff1);              \
        float4 Qc = *reinterpret_cast<const float4*>(sp + qoff2);              \
        Qa.x *= mlo; Qa.y *= mlo; Qa.z *= mlo; Qa.w *= mlo;                    \
        *reinterpret_cast<float2*>(opc) = make_float2(                         \
            wT0*Qa.x + wT1*Qa.z + wT2*Qb.x + wT3*Qb.z + wT4*Qc.x,              \
            wT0*Qa.y + wT1*Qa.w + wT2*Qb.y + wT3*Qb.w + wT4*Qc.y);             \
        *reinterpret_cast<float2*>(opc + 1 * HW) = make_float2(                \
            wT0*Qa.z + wT1*Qb.x + wT2*Qb.z + wT3*Qc.x + wT4*Qc.z,              \
            wT0*Qa.w + wT1*Qb.y + wT2*Qb.w + wT3*Qc.y + wT4*Qc.w);             \
        Qa = *reinterpret_cast<const float4*>(sp + qoff3);                     \
        *reinterpret_cast<float2*>(opc + 2 * HW) = make_float2(                \
            wT0*Qb.x + wT1*Qb.z + wT2*Qc.x + wT3*Qc.z + wT4*Qa.x,              \
            wT0*Qb.y + wT1*Qb.w + wT2*Qc.y + wT3*Qc.w + wT4*Qa.y);             \
        *reinterpret_cast<float2*>(opc + 3 * HW) = make_float2(                \
            wT0*Qb.z + wT1*Qc.x + wT2*Qc.z + wT3*Qa.x + wT4*Qa.z,              \
            wT0*Qb.w + wT1*Qc.y + wT2*Qc.w + wT3*Qa.y + wT4*Qa.w);             \
        Qb = *reinterpret_cast<const float4*>(sp + qoff4);                     \
        *reinterpret_cast<float2*>(opc + 4 * HW) = make_float2(                \
            wT0*Qc.x + wT1*Qc.z + wT2*Qa.x + wT3*Qa.z + wT4*Qb.x,              \
            wT0*Qc.y + wT1*Qc.w + wT2*Qa.y + wT3*Qa.w + wT4*Qb.y);             \
        *reinterpret_cast<float2*>(opc + 5 * HW) = make_float2(                \
            wT0*Qc.z + wT1*Qa.x + wT2*Qa.z + wT3*Qb.x + wT4*Qb.z,              \
            wT0*Qc.w + wT1*Qa.y + wT2*Qa.w + wT3*Qb.y + wT4*Qb.w);             \
        Qc = *reinterpret_cast<const float4*>(sp + qoff5);                     \
        Qc.x *= mhi; Qc.y *= mhi; Qc.z *= mhi; Qc.w *= mhi;                    \
        *reinterpret_cast<float2*>(opc + 6 * HW) = make_float2(                \
            wT0*Qa.x + wT1*Qa.z + wT2*Qb.x + wT3*Qb.z + wT4*Qc.x,              \
            wT0*Qa.y + wT1*Qa.w + wT2*Qb.y + wT3*Qb.w + wT4*Qc.y);             \
        *reinterpret_cast<float2*>(opc + 7 * HW) = make_float2(                \
            wT0*Qa.z + wT1*Qb.x + wT2*Qb.z + wT3*Qc.x + wT4*Qc.z,              \
            wT0*Qa.w + wT1*Qb.y + wT2*Qb.w + wT3*Qc.y + wT4*Qc.w);             \
    }
    // =========================================================================

    // ---- prologue: rows h0-2, h0-1 into xbuf[0][0..1] ----
    {
        float4 v0 = {0,0,0,0}, v1 = {0,0,0,0}, u0 = {0,0,0,0}, u1 = {0,0,0,0};
        if (wvA && h0 - 2 >= 0) v0 = *reinterpret_cast<const float4*>(gA + (size_t)(h0 - 2) * WW);
        if (wvA && h0 - 1 >= 0) v1 = *reinterpret_cast<const float4*>(gA + (size_t)(h0 - 1) * WW);
        *reinterpret_cast<float4*>(xsA00) = v0;
        *reinterpret_cast<float4*>(xsA01) = v1;
        if (hasB) {
            if (wvB && h0 - 2 >= 0) u0 = *reinterpret_cast<const float4*>(gB + (size_t)(h0 - 2) * WW);
            if (wvB && h0 - 1 >= 0) u1 = *reinterpret_cast<const float4*>(gB + (size_t)(h0 - 1) * WW);
            *reinterpret_cast<float4*>(xsB00) = u0;
            *reinterpret_cast<float4*>(xsB01) = u1;
        }
    }
    __syncthreads();

    // ---- warmup: ii = 0..3 (no phase C; s stored at ii=2 (buf2), ii=3 (buf0)) ----
    { PREFETCH(0) WCONV_ROWS(0) RING_SHIFT() opc += 2 * WW; COMMIT(0) __syncthreads(); }
    { PREFETCH(1) WCONV_ROWS(1) RING_SHIFT() opc += 2 * WW; COMMIT(1) __syncthreads(); }
    { PREFETCH(2) WCONV_ROWS(0) STORE_S(sbW2) RING_SHIFT() opc += 2 * WW; COMMIT(0) __syncthreads(); }
    { PREFETCH(3) WCONV_ROWS(1) STORE_S(sbW0) RING_SHIFT() opc += 2 * WW; COMMIT(1) __syncthreads(); }

    // ---- steady: ii = 4..15, unroll 6 so ii%2 and ii%3 are static per copy ----
    #pragma unroll 6
    for (int ii = 4; ii < 16; ++ii) {
        const int cur = ii & 1;
        PREFETCH(ii)
        WCONV_ROWS(cur)
        // write s into buf ii%3
        {
            const int j = ii % 3;
            STORE_S(j == 0 ? sbW0 : (j == 1 ? sbW1 : sbW2))
        }
        RING_SHIFT()
        if ((ii & 1) == 0) {
            // phase C over 4 rows: bufs (ii-2)%3 (r<2) and (ii-1)%3 (r>=2)
            const int b0 = (ii - 2) % 3;
            const float* spL =
                (b0 == 0) ? ((r < 2) ? spP0 : spP1)
              : (b0 == 1) ? ((r < 2) ? spP1 : spP2)
                          : ((r < 2) ? spP2 : spP0);
            PHASE_C16(spL)
        }
        opc += 2 * WW;
        COMMIT(cur)
        __syncthreads();
    }

    // ---- tail ii = 16: full body with phase C (b0 = 14%3 = 2) ----
    {
        PREFETCH(16)
        WCONV_ROWS(0)
        STORE_S(sbW1)          // 16 % 3 == 1
        RING_SHIFT()
        {
            const float* spL = (r < 2) ? spP2 : spP0;   // bufs for jj=14,15
            PHASE_C16(spL)
        }
        opc += 2 * WW;
        COMMIT(0)
        __syncthreads();
    }

    // ---- tail ii = 17: no prefetch/commit; store s (buf 17%3 = 2) ----
    {
        WCONV_ROWS(1)
        STORE_S(sbW2)
        opc += 2 * WW;
        __syncthreads();
    }

    // ---- epilogue: consume jj = 16 (buf 1) and jj = 17 (buf 2) ----
    {
        const float* spL = (r < 2) ? spP1 : spP2;
        // opc advanced 18x: points at row h0 + 28 + r
        PHASE_C16(spL)
    }

#undef PREFETCH
#undef WCONV_ROWS
#undef STORE_S
#undef RING_SHIFT
#undef COMMIT
#undef PHASE_C16
}

extern "C" void kernel_launch(void* const* d_in, const int* in_sizes, int n_in,
                              void* d_out, int out_size)
{
    const float* x  = (const float*)d_in[0];
    const float* w1 = (const float*)d_in[1];
    const float* w2 = (const float*)d_in[2];
    const float* w3 = (const float*)d_in[3];
    float* out = (float*)d_out;

    // 24 (n*c) * 8 (w tiles) * 8 (h chunks) = 1536 blocks
    sepconv3d_fused<<<NN * CC * (WW / WT) * (HH / HC), 256>>>(x, w1, w2, w3, out);
}

// round 15
// speedup vs baseline: 1.1032x; 1.1032x over previous
#include <cuda_runtime.h>
#include <cstdint>

// SeparableConv3D: x[8,3,32,256,256] fp32, depthwise K=5 cross-correlation
// along W, then H, then T, zero 'same' padding each stage.
//
// R11 pipeline, t-major staging (stride 38), 8t x 1w phase C:
//   phase A: prefetch 2 x-rows into regs (item A: all; item B: threads 0-63),
//            commit via aligned STS.128 at iter end
//   phase B (lane=t, wg=w-quad): W-conv via 4 aligned LDS.64 + H-conv ring
//            (shift by 2), store s -> sbufT[w][t] (8x STS.32, coalesced)
//   phase C (all 256 threads; thread=(w, t-seg, row)): T-conv = 6 LDS.64
//            (12 floats -> 8 outputs, 1.5x amp, conflict-free stride 38),
//            rolling 4-pair consume; 8x STG.32 (128B-coalesced per warp)
//   ONE __syncthreads per 2 h-rows.

#define NN 8
#define CC 3
#define TT 32
#define HH 256
#define WW 256
#define KK 5

#define WT 32                 // w outputs per block
#define HC 32                 // h rows per block -> grid = 24*8*8 = 1536
#define NIT ((HC + 4) / 2)    // 18 iterations of 2 rows
#define XSTRIDE 44            // x slab row stride (conflict-free)
#define STR_T 38              // sbufT per-w stride: 6w mod 32 distinct over 16 lanes

__global__ void __launch_bounds__(256, 4)
sepconv3d_fused(const float* __restrict__ x,
                const float* __restrict__ w1,   // along W
                const float* __restrict__ w2,   // along H
                const float* __restrict__ w3,   // along T
                float* __restrict__ out)
{
    __shared__ float xbuf[2][2][TT * XSTRIDE];     // [buf][row]
    __shared__ float sbufT[2][2][WT * STR_T];      // [buf][row][w][t]

    const int tid  = threadIdx.x;
    const int lane = tid & 31;     // phase B: = t ; phase C: = w
    const int wg   = tid >> 5;     // phase B: w-quad

    const int bid = blockIdx.x;               // 0..1535
    const int nc  = bid >> 6;                  // n*3+c
    const int rem = bid & 63;
    const int wt  = rem >> 3;                   // 0..7
    const int hcb = rem & 7;                    // 0..7
    const int c   = nc % CC;

    const int w0 = wt * WT;
    const int h0 = hcb * HC;
    const size_t HW = (size_t)HH * WW;

    const float wW0 = w1[c*KK+0], wW1 = w1[c*KK+1], wW2 = w1[c*KK+2], wW3 = w1[c*KK+3], wW4 = w1[c*KK+4];
    const float wH0 = w2[c*KK+0], wH1 = w2[c*KK+1], wH2 = w2[c*KK+2], wH3 = w2[c*KK+3], wH4 = w2[c*KK+4];
    const float wT0 = w3[c*KK+0], wT1 = w3[c*KK+1], wT2 = w3[c*KK+2], wT3 = w3[c*KK+3], wT4 = w3[c*KK+4];

    const float* xb = x   + (size_t)nc * (TT * HW);
    float*       ob = out + (size_t)nc * (TT * HW);

    // ---- slab-load geometry: item A = tid (all), item B = threads 0-63 ----
    const int trA = tid / 10,  qA = tid - trA * 10;
    const bool hasB = (tid < 64);
    const int iB  = 256 + tid;
    const int trB = iB / 10,   qB = iB - trB * 10;
    const int gwA = w0 - 4 + 4 * qA;
    const int gwB = w0 - 4 + 4 * qB;
    const bool wvA = (gwA >= 0) && (gwA < WW);
    const bool wvB = hasB && (gwB >= 0) && (gwB < WW);
    const float* gA = xb + (size_t)trA * HW + (wvA ? gwA : 0);   // + h*WW
    const float* gB = xb + (size_t)trB * HW + (wvB ? gwB : 0);

    // smem commit addresses (aligned STS.128)
    float* const xsA00 = &xbuf[0][0][trA * XSTRIDE + 4 * qA];
    float* const xsA01 = &xbuf[0][1][trA * XSTRIDE + 4 * qA];
    float* const xsA10 = &xbuf[1][0][trA * XSTRIDE + 4 * qA];
    float* const xsA11 = &xbuf[1][1][trA * XSTRIDE + 4 * qA];
    float* const xsB00 = &xbuf[0][0][trB * XSTRIDE + 4 * qB];
    float* const xsB01 = &xbuf[0][1][trB * XSTRIDE + 4 * qB];
    float* const xsB10 = &xbuf[1][0][trB * XSTRIDE + 4 * qB];
    float* const xsB11 = &xbuf[1][1][trB * XSTRIDE + 4 * qB];

    // ---- phase C geometry: thread = (w, t-seg, row) ----
    const int wC  = tid & 31;          // w within tile
    const int seg = (tid >> 5) & 3;    // 8t segment
    const int rr  = tid >> 7;          // row 0/1
    const int t0  = 8 * seg;
    const int cbase = wC * STR_T;
    // pair offsets: Pk = s[t0-2+2k, t0-1+2k] for this w
    const int e0 = cbase + ((seg == 0) ? 0 : (t0 - 2));     // masked if seg==0
    const int e1 = cbase + t0;                               // P1..P4 at e1+0,2,4,6
    const int e5 = cbase + ((seg == 3) ? 30 : (t0 + 8));    // masked if seg==3
    const float mlo = (seg == 0) ? 0.f : 1.f;   // zero-pad t<0
    const float mhi = (seg == 3) ? 0.f : 1.f;   // zero-pad t>31
    // op advances 2 rows per iter; at iter ii it points at row h0 + 2ii - 6 + rr
    float* op = ob + (size_t)t0 * HW + w0 + wC
                   + (size_t)(h0 + rr) * WW - 6 * WW;

    // H-conv register ring: g1..g4 = W-conv of the last 4 input rows
    float4 g1 = {0,0,0,0}, g2 = {0,0,0,0}, g3 = {0,0,0,0}, g4 = {0,0,0,0};
    const int scolbase = 4 * wg;
    // phase-B store bases: column t=lane of w-rows 4wg..4wg+3
    float* const sbB00 = &sbufT[0][0][scolbase * STR_T + lane];
    float* const sbB01 = &sbufT[0][1][scolbase * STR_T + lane];
    float* const sbB10 = &sbufT[1][0][scolbase * STR_T + lane];
    float* const sbB11 = &sbufT[1][1][scolbase * STR_T + lane];

    // ---- prologue: rows h0-2, h0-1 into xbuf[0][0..1] ----
    {
        float4 v0 = {0,0,0,0}, v1 = {0,0,0,0}, u0 = {0,0,0,0}, u1 = {0,0,0,0};
        if (wvA && h0 - 2 >= 0) v0 = *reinterpret_cast<const float4*>(gA + (size_t)(h0 - 2) * WW);
        if (wvA && h0 - 1 >= 0) v1 = *reinterpret_cast<const float4*>(gA + (size_t)(h0 - 1) * WW);
        *reinterpret_cast<float4*>(xsA00) = v0;
        *reinterpret_cast<float4*>(xsA01) = v1;
        if (hasB) {
            if (wvB && h0 - 2 >= 0) u0 = *reinterpret_cast<const float4*>(gB + (size_t)(h0 - 2) * WW);
            if (wvB && h0 - 1 >= 0) u1 = *reinterpret_cast<const float4*>(gB + (size_t)(h0 - 1) * WW);
            *reinterpret_cast<float4*>(xsB00) = u0;
            *reinterpret_cast<float4*>(xsB01) = u1;
        }
    }
    __syncthreads();

#define PHASE_C8(SRC)                                                          \
    {                                                                          \
        const float* sp = sbufT[SRC][rr];                                      \
        float2 P0 = *reinterpret_cast<const float2*>(sp + e0);                 \
        P0.x *= mlo; P0.y *= mlo;                                              \
        float2 P1 = *reinterpret_cast<const float2*>(sp + e1);                 \
        float2 P2 = *reinterpret_cast<const float2*>(sp + e1 + 2);             \
        op[0]      = wT0*P0.x + wT1*P0.y + wT2*P1.x + wT3*P1.y + wT4*P2.x;     \
        op[1 * HW] = wT0*P0.y + wT1*P1.x + wT2*P1.y + wT3*P2.x + wT4*P2.y;     \
        float2 P3 = *reinterpret_cast<const float2*>(sp + e1 + 4);             \
        op[2 * HW] = wT0*P1.x + wT1*P1.y + wT2*P2.x + wT3*P2.y + wT4*P3.x;     \
        op[3 * HW] = wT0*P1.y + wT1*P2.x + wT2*P2.y + wT3*P3.x + wT4*P3.y;     \
        float2 P4 = *reinterpret_cast<const float2*>(sp + e1 + 6);             \
        op[4 * HW] = wT0*P2.x + wT1*P2.y + wT2*P3.x + wT3*P3.y + wT4*P4.x;     \
        op[5 * HW] = wT0*P2.y + wT1*P3.x + wT2*P3.y + wT3*P4.x + wT4*P4.y;     \
        float2 P5 = *reinterpret_cast<const float2*>(sp + e5);                 \
        P5.x *= mhi; P5.y *= mhi;                                              \
        op[6 * HW] = wT0*P3.x + wT1*P3.y + wT2*P4.x + wT3*P4.y + wT4*P5.x;     \
        op[7 * HW] = wT0*P3.y + wT1*P4.x + wT2*P4.y + wT3*P5.x + wT4*P5.y;     \
    }

    #pragma unroll 2
    for (int ii = 0; ii < NIT; ++ii) {
        const int cur = ii & 1;

        // ---- 1. prefetch rows h0+2ii, h0+2ii+1 (for next iteration) ----
        float4 pa0 = {0,0,0,0}, pa1 = {0,0,0,0}, pb0 = {0,0,0,0}, pb1 = {0,0,0,0};
        {
            const bool iv = (ii + 1 < NIT);
            const int ha = h0 + 2 * ii;
            const int hb = ha + 1;
            if (iv && wvA && ha < HH) pa0 = *reinterpret_cast<const float4*>(gA + (size_t)ha * WW);
            if (iv && wvA && hb < HH) pa1 = *reinterpret_cast<const float4*>(gA + (size_t)hb * WW);
            if (iv && wvB && ha < HH) pb0 = *reinterpret_cast<const float4*>(gB + (size_t)ha * WW);
            if (iv && wvB && hb < HH) pb1 = *reinterpret_cast<const float4*>(gB + (size_t)hb * WW);
        }

        // ---- 2. phase B: W-conv both rows (4x LDS.64 each), H-conv -> sbufT[cur] ----
        float4 r_a, r_b;
        {
            const float* row0 = &xbuf[cur][0][lane * XSTRIDE + scolbase + 2];
            float2 a0 = *reinterpret_cast<const float2*>(row0);       // x[w-2,w-1]
            float2 a1 = *reinterpret_cast<const float2*>(row0 + 2);   // x[w  ,w+1]
            float2 a2 = *reinterpret_cast<const float2*>(row0 + 4);   // x[w+2,w+3]
            float2 a3 = *reinterpret_cast<const float2*>(row0 + 6);   // x[w+4,w+5]
            r_a.x = wW0*a0.x + wW1*a0.y + wW2*a1.x + wW3*a1.y + wW4*a2.x;
            r_a.y = wW0*a0.y + wW1*a1.x + wW2*a1.y + wW3*a2.x + wW4*a2.y;
            r_a.z = wW0*a1.x + wW1*a1.y + wW2*a2.x + wW3*a2.y + wW4*a3.x;
            r_a.w = wW0*a1.y + wW1*a2.x + wW2*a2.y + wW3*a3.x + wW4*a3.y;

            const float* row1 = &xbuf[cur][1][lane * XSTRIDE + scolbase + 2];
            float2 b0 = *reinterpret_cast<const float2*>(row1);
            float2 b1 = *reinterpret_cast<const float2*>(row1 + 2);
            float2 b2 = *reinterpret_cast<const float2*>(row1 + 4);
            float2 b3 = *reinterpret_cast<const float2*>(row1 + 6);
            r_b.x = wW0*b0.x + wW1*b0.y + wW2*b1.x + wW3*b1.y + wW4*b2.x;
            r_b.y = wW0*b0.y + wW1*b1.x + wW2*b1.y + wW3*b2.x + wW4*b2.y;
            r_b.z = wW0*b1.x + wW1*b1.y + wW2*b2.x + wW3*b2.y + wW4*b3.x;
            r_b.w = wW0*b1.y + wW1*b2.x + wW2*b2.y + wW3*b3.x + wW4*b3.y;
        }

        if (ii >= 2) {
            float* sa = cur ? sbB10 : sbB00;   // row a, w-rows 4wg..4wg+3, col t=lane
            float* sb = cur ? sbB11 : sbB01;   // row b
            sa[0 * STR_T] = wH0*g1.x + wH1*g2.x + wH2*g3.x + wH3*g4.x + wH4*r_a.x;
            sa[1 * STR_T] = wH0*g1.y + wH1*g2.y + wH2*g3.y + wH3*g4.y + wH4*r_a.y;
            sa[2 * STR_T] = wH0*g1.z + wH1*g2.z + wH2*g3.z + wH3*g4.z + wH4*r_a.z;
            sa[3 * STR_T] = wH0*g1.w + wH1*g2.w + wH2*g3.w + wH3*g4.w + wH4*r_a.w;
            sb[0 * STR_T] = wH0*g2.x + wH1*g3.x + wH2*g4.x + wH3*r_a.x + wH4*r_b.x;
            sb[1 * STR_T] = wH0*g2.y + wH1*g3.y + wH2*g4.y + wH3*r_a.y + wH4*r_b.y;
            sb[2 * STR_T] = wH0*g2.z + wH1*g3.z + wH2*g4.z + wH3*r_a.z + wH4*r_b.z;
            sb[3 * STR_T] = wH0*g2.w + wH1*g3.w + wH2*g4.w + wH3*r_a.w + wH4*r_b.w;
        }
        // ring shift by 2 (rename)
        g1 = g3; g2 = g4; g3 = r_a; g4 = r_b;

        // ---- 3. phase C: T-conv from PREVIOUS sbufT; 8t x 1w per thread ----
        if (ii >= 3) {
            PHASE_C8(cur ^ 1)
        }
        op += 2 * WW;

        // ---- 4. commit prefetched rows into xbuf[cur^1] ----
        *reinterpret_cast<float4*>(cur ? xsA00 : xsA10) = pa0;
        *reinterpret_cast<float4*>(cur ? xsA01 : xsA11) = pa1;
        if (hasB) {
            *reinterpret_cast<float4*>(cur ? xsB00 : xsB10) = pb0;
            *reinterpret_cast<float4*>(cur ? xsB01 : xsB11) = pb1;
        }

        __syncthreads();
        // barrier orders: xbuf[cur^1] STS vs next-iter LDS; sbufT[cur] writes vs
        // next-iter phase-C reads; phase-C reads of sbufT[cur^1] vs iter+1 writes.
    }

    // ---- epilogue: last 2 output rows from sbufT[(NIT-1)&1] ----
    // op has advanced 2*NIT rows: points at row h0 + 30 + rr
    PHASE_C8((NIT - 1) & 1)

#undef PHASE_C8
}

extern "C" void kernel_launch(void* const* d_in, const int* in_sizes, int n_in,
                              void* d_out, int out_size)
{
    const float* x  = (const float*)d_in[0];
    const float* w1 = (const float*)d_in[1];
    const float* w2 = (const float*)d_in[2];
    const float* w3 = (const float*)d_in[3];
    float* out = (float*)d_out;

    // 24 (n*c) * 8 (w tiles) * 8 (h chunks) = 1536 blocks
    sepconv3d_fused<<<NN * CC * (WW / WT) * (HH / HC), 256>>>(x, w1, w2, w3, out);
}

// round 16
// speedup vs baseline: 1.3675x; 1.2396x over previous
#include <cuda_runtime.h>
#include <cstdint>

// SeparableConv3D: x[8,3,32,256,256] fp32, depthwise K=5 cross-correlation
// along W, then H, then T, zero 'same' padding each stage.
//
// R15 pipeline with a 3-deep cp.async ring for the x slab:
//   phase A: cp.async (LDGSTS) rows for iteration ii+2 into xbuf[(ii+2)%3],
//            one commit group per iteration, wait_group 1 before the barrier
//            (i.e. only the group issued a FULL iteration ago must be done)
//   phase B (lane=t, wg=w-quad): W-conv via 4 aligned LDS.64 + H-conv ring
//            (shift by 2), store s -> sbufT[w][t] (t-major, stride 38)
//   phase C (all 256 threads; thread=(w, t-seg, row)): T-conv = 6 LDS.64
//            (12 floats -> 8 outputs, 1.5x amp), 8x STG.32 coalesced
//   ONE __syncthreads per 2 h-rows; unroll 6 makes all %2/%3 indices static.

#define NN 8
#define CC 3
#define TT 32
#define HH 256
#define WW 256
#define KK 5

#define WT 32                 // w outputs per block
#define HC 32                 // h rows per block -> grid = 24*8*8 = 1536
#define NIT ((HC + 4) / 2)    // 18 iterations of 2 rows
#define XSTRIDE 44            // x slab row stride (conflict-free)
#define RB (TT * XSTRIDE * 4) // bytes per x row-buffer = 5632
#define STR_T 38              // sbufT per-w stride (conflict-free LDS.64)

__device__ __forceinline__ void cp16(uint32_t dst, const float* src, bool pred) {
    int sz = pred ? 16 : 0;   // src-size 0 -> 16B zero-fill (pad rows)
    asm volatile("cp.async.cg.shared.global [%0], [%1], 16, %2;\n"
                 :: "r"(dst), "l"(src), "r"(sz));
}
__device__ __forceinline__ void cp_commit() {
    asm volatile("cp.async.commit_group;\n" ::: "memory");
}
__device__ __forceinline__ void cp_wait0() {
    asm volatile("cp.async.wait_group 0;\n" ::: "memory");
}
__device__ __forceinline__ void cp_wait1() {
    asm volatile("cp.async.wait_group 1;\n" ::: "memory");
}

__global__ void __launch_bounds__(256, 4)
sepconv3d_fused(const float* __restrict__ x,
                const float* __restrict__ w1,   // along W
                const float* __restrict__ w2,   // along H
                const float* __restrict__ w3,   // along T
                float* __restrict__ out)
{
    __shared__ float xbuf[3][2][TT * XSTRIDE];     // [buf][row] cp.async ring
    __shared__ float sbufT[2][2][WT * STR_T];      // [buf][row][w][t]

    const int tid  = threadIdx.x;
    const int lane = tid & 31;     // phase B: = t ; phase C: = w
    const int wg   = tid >> 5;     // phase B: w-quad

    const int bid = blockIdx.x;               // 0..1535
    const int nc  = bid >> 6;                  // n*3+c
    const int rem = bid & 63;
    const int wt  = rem >> 3;                   // 0..7
    const int hcb = rem & 7;                    // 0..7
    const int c   = nc % CC;

    const int w0 = wt * WT;
    const int h0 = hcb * HC;
    const size_t HW = (size_t)HH * WW;

    const float wW0 = w1[c*KK+0], wW1 = w1[c*KK+1], wW2 = w1[c*KK+2], wW3 = w1[c*KK+3], wW4 = w1[c*KK+4];
    const float wH0 = w2[c*KK+0], wH1 = w2[c*KK+1], wH2 = w2[c*KK+2], wH3 = w2[c*KK+3], wH4 = w2[c*KK+4];
    const float wT0 = w3[c*KK+0], wT1 = w3[c*KK+1], wT2 = w3[c*KK+2], wT3 = w3[c*KK+3], wT4 = w3[c*KK+4];

    const float* xb = x   + (size_t)nc * (TT * HW);
    float*       ob = out + (size_t)nc * (TT * HW);

    // ---- slab-load geometry: item A = tid (all), item B = threads 0-63 ----
    const int trA = tid / 10,  qA = tid - trA * 10;
    const bool hasB = (tid < 64);
    const int iB  = 256 + tid;
    const int trB = iB / 10,   qB = iB - trB * 10;
    const int gwA = w0 - 4 + 4 * qA;
    const int gwB = w0 - 4 + 4 * qB;
    const bool wvA = (gwA >= 0) && (gwA < WW);
    const bool wvB = hasB && (gwB >= 0) && (gwB < WW);
    const float* gA = xb + (size_t)trA * HW + (wvA ? gwA : 0);   // + h*WW
    const float* gB = xb + (size_t)trB * HW + (wvB ? gwB : 0);

    // cp.async destination base addresses (byte offsets into the ring)
    const uint32_t xbase = (uint32_t)__cvta_generic_to_shared(&xbuf[0][0][0]);
    const uint32_t dA = xbase + (uint32_t)(trA * XSTRIDE + 4 * qA) * 4u;
    const uint32_t dB = xbase + (uint32_t)(trB * XSTRIDE + 4 * qB) * 4u;

    // ---- phase C geometry: thread = (w, t-seg, row) ----
    const int wC  = tid & 31;          // w within tile
    const int seg = (tid >> 5) & 3;    // 8t segment
    const int rr  = tid >> 7;          // row 0/1
    const int t0  = 8 * seg;
    const int cbase = wC * STR_T;
    const int e0 = cbase + ((seg == 0) ? 0 : (t0 - 2));     // masked if seg==0
    const int e1 = cbase + t0;                               // P1..P4 at e1+0,2,4,6
    const int e5 = cbase + ((seg == 3) ? 30 : (t0 + 8));    // masked if seg==3
    const float mlo = (seg == 0) ? 0.f : 1.f;   // zero-pad t<0
    const float mhi = (seg == 3) ? 0.f : 1.f;   // zero-pad t>31
    // op advances 2 rows per iter; at iter ii it points at row h0 + 2ii - 6 + rr
    float* op = ob + (size_t)t0 * HW + w0 + wC
                   + (size_t)(h0 + rr) * WW - 6 * WW;

    // H-conv register ring: g1..g4 = W-conv of the last 4 input rows
    float4 g1 = {0,0,0,0}, g2 = {0,0,0,0}, g3 = {0,0,0,0}, g4 = {0,0,0,0};
    const int scolbase = 4 * wg;
    float* const sbB00 = &sbufT[0][0][scolbase * STR_T + lane];
    float* const sbB01 = &sbufT[0][1][scolbase * STR_T + lane];
    float* const sbB10 = &sbufT[1][0][scolbase * STR_T + lane];
    float* const sbB11 = &sbufT[1][1][scolbase * STR_T + lane];

    // ---- prologue: buf0 <- rows h0-2,h0-1 ; buf1 <- rows h0,h0+1 ----
    {
        int h = h0 - 2;
        bool pA = wvA && (h >= 0);
        cp16(dA + 0u * RB, gA + (size_t)(pA ? h : 0) * WW, pA);
        if (hasB) { bool pB = wvB && (h >= 0);
                    cp16(dB + 0u * RB, gB + (size_t)(pB ? h : 0) * WW, pB); }
        h = h0 - 1;
        pA = wvA && (h >= 0);
        cp16(dA + 1u * RB, gA + (size_t)(pA ? h : 0) * WW, pA);
        if (hasB) { bool pB = wvB && (h >= 0);
                    cp16(dB + 1u * RB, gB + (size_t)(pB ? h : 0) * WW, pB); }
        cp_commit();
        cp16(dA + 2u * RB, gA + (size_t)h0 * WW, wvA);
        cp16(dA + 3u * RB, gA + (size_t)(h0 + 1) * WW, wvA);
        if (hasB) {
            cp16(dB + 2u * RB, gB + (size_t)h0 * WW, wvB);
            cp16(dB + 3u * RB, gB + (size_t)(h0 + 1) * WW, wvB);
        }
        cp_commit();
        cp_wait0();
    }
    __syncthreads();

#define PHASE_C8(SRC)                                                          \
    {                                                                          \
        const float* sp = sbufT[SRC][rr];                                      \
        float2 P0 = *reinterpret_cast<const float2*>(sp + e0);                 \
        P0.x *= mlo; P0.y *= mlo;                                              \
        float2 P1 = *reinterpret_cast<const float2*>(sp + e1);                 \
        float2 P2 = *reinterpret_cast<const float2*>(sp + e1 + 2);             \
        op[0]      = wT0*P0.x + wT1*P0.y + wT2*P1.x + wT3*P1.y + wT4*P2.x;     \
        op[1 * HW] = wT0*P0.y + wT1*P1.x + wT2*P1.y + wT3*P2.x + wT4*P2.y;     \
        float2 P3 = *reinterpret_cast<const float2*>(sp + e1 + 4);             \
        op[2 * HW] = wT0*P1.x + wT1*P1.y + wT2*P2.x + wT3*P2.y + wT4*P3.x;     \
        op[3 * HW] = wT0*P1.y + wT1*P2.x + wT2*P2.y + wT3*P3.x + wT4*P3.y;     \
        float2 P4 = *reinterpret_cast<const float2*>(sp + e1 + 6);             \
        op[4 * HW] = wT0*P2.x + wT1*P2.y + wT2*P3.x + wT3*P3.y + wT4*P4.x;     \
        op[5 * HW] = wT0*P2.y + wT1*P3.x + wT2*P3.y + wT3*P4.x + wT4*P4.y;     \
        float2 P5 = *reinterpret_cast<const float2*>(sp + e5);                 \
        P5.x *= mhi; P5.y *= mhi;                                              \
        op[6 * HW] = wT0*P3.x + wT1*P3.y + wT2*P4.x + wT3*P4.y + wT4*P5.x;     \
        op[7 * HW] = wT0*P3.y + wT1*P4.x + wT2*P4.y + wT3*P5.x + wT4*P5.y;     \
    }

    #pragma unroll 6
    for (int ii = 0; ii < NIT; ++ii) {
        const int cur3 = ii % 3;         // x ring buffer to read (static)
        const int cur2 = ii & 1;         // sbufT buffer to write (static)

        // ---- 1. issue cp.async group for iteration ii+2 into buf (ii+2)%3 ----
        {
            const int jd = (ii + 2) % 3;                 // static under unroll
            const int ha = h0 + 2 * ii + 2;
            const int hb = ha + 1;
            const bool live = (ii < NIT - 2);            // dead groups zero-fill
            bool va = live && wvA && (ha < HH);
            bool vb = live && wvA && (hb < HH);
            cp16(dA + (uint32_t)(2 * jd + 0) * RB, gA + (size_t)(va ? ha : 0) * WW, va);
            cp16(dA + (uint32_t)(2 * jd + 1) * RB, gA + (size_t)(vb ? hb : 0) * WW, vb);
            if (hasB) {
                bool ua = live && wvB && (ha < HH);
                bool ub = live && wvB && (hb < HH);
                cp16(dB + (uint32_t)(2 * jd + 0) * RB, gB + (size_t)(ua ? ha : 0) * WW, ua);
                cp16(dB + (uint32_t)(2 * jd + 1) * RB, gB + (size_t)(ub ? hb : 0) * WW, ub);
            }
            cp_commit();
        }

        // ---- 2. phase B: W-conv both rows (4x LDS.64 each), H-conv -> sbufT[cur2] ----
        float4 r_a, r_b;
        {
            const float* row0 = &xbuf[cur3][0][lane * XSTRIDE + scolbase + 2];
            float2 a0 = *reinterpret_cast<const float2*>(row0);       // x[w-2,w-1]
            float2 a1 = *reinterpret_cast<const float2*>(row0 + 2);   // x[w  ,w+1]
            float2 a2 = *reinterpret_cast<const float2*>(row0 + 4);   // x[w+2,w+3]
            float2 a3 = *reinterpret_cast<const float2*>(row0 + 6);   // x[w+4,w+5]
            r_a.x = wW0*a0.x + wW1*a0.y + wW2*a1.x + wW3*a1.y + wW4*a2.x;
            r_a.y = wW0*a0.y + wW1*a1.x + wW2*a1.y + wW3*a2.x + wW4*a2.y;
            r_a.z = wW0*a1.x + wW1*a1.y + wW2*a2.x + wW3*a2.y + wW4*a3.x;
            r_a.w = wW0*a1.y + wW1*a2.x + wW2*a2.y + wW3*a3.x + wW4*a3.y;

            const float* row1 = &xbuf[cur3][1][lane * XSTRIDE + scolbase + 2];
            float2 b0 = *reinterpret_cast<const float2*>(row1);
            float2 b1 = *reinterpret_cast<const float2*>(row1 + 2);
            float2 b2 = *reinterpret_cast<const float2*>(row1 + 4);
            float2 b3 = *reinterpret_cast<const float2*>(row1 + 6);
            r_b.x = wW0*b0.x + wW1*b0.y + wW2*b1.x + wW3*b1.y + wW4*b2.x;
            r_b.y = wW0*b0.y + wW1*b1.x + wW2*b1.y + wW3*b2.x + wW4*b2.y;
            r_b.z = wW0*b1.x + wW1*b1.y + wW2*b2.x + wW3*b2.y + wW4*b3.x;
            r_b.w = wW0*b1.y + wW1*b2.x + wW2*b2.y + wW3*b3.x + wW4*b3.y;
        }

        if (ii >= 2) {
            float* sa = cur2 ? sbB10 : sbB00;   // row a, w-rows 4wg..4wg+3, col t=lane
            float* sb = cur2 ? sbB11 : sbB01;   // row b
            sa[0 * STR_T] = wH0*g1.x + wH1*g2.x + wH2*g3.x + wH3*g4.x + wH4*r_a.x;
            sa[1 * STR_T] = wH0*g1.y + wH1*g2.y + wH2*g3.y + wH3*g4.y + wH4*r_a.y;
            sa[2 * STR_T] = wH0*g1.z + wH1*g2.z + wH2*g3.z + wH3*g4.z + wH4*r_a.z;
            sa[3 * STR_T] = wH0*g1.w + wH1*g2.w + wH2*g3.w + wH3*g4.w + wH4*r_a.w;
            sb[0 * STR_T] = wH0*g2.x + wH1*g3.x + wH2*g4.x + wH3*r_a.x + wH4*r_b.x;
            sb[1 * STR_T] = wH0*g2.y + wH1*g3.y + wH2*g4.y + wH3*r_a.y + wH4*r_b.y;
            sb[2 * STR_T] = wH0*g2.z + wH1*g3.z + wH2*g4.z + wH3*r_a.z + wH4*r_b.z;
            sb[3 * STR_T] = wH0*g2.w + wH1*g3.w + wH2*g4.w + wH3*r_a.w + wH4*r_b.w;
        }
        // ring shift by 2 (rename)
        g1 = g3; g2 = g4; g3 = r_a; g4 = r_b;

        // ---- 3. phase C: T-conv from PREVIOUS sbufT; 8t x 1w per thread ----
        if (ii >= 3) {
            PHASE_C8(cur2 ^ 1)
        }
        op += 2 * WW;

        // ---- 4. wait for the group issued ONE iteration ago, then barrier ----
        cp_wait1();
        __syncthreads();
        // wait_group 1: the group issued at iter ii-1 (data for iter ii+1) is
        // complete; the group issued this iter may remain in flight.
        // barrier orders: sbufT[cur2] writes vs next-iter phase-C reads;
        // phase-C reads of sbufT[cur2^1] vs its rewrite at iter ii+1;
        // cp.async-completed xbuf data vs all threads' next-iter LDS.
    }

    // ---- epilogue: last 2 output rows from sbufT[(NIT-1)&1] ----
    // op has advanced 2*NIT rows: points at row h0 + 30 + rr
    PHASE_C8((NIT - 1) & 1)

#undef PHASE_C8
}

extern "C" void kernel_launch(void* const* d_in, const int* in_sizes, int n_in,
                              void* d_out, int out_size)
{
    const float* x  = (const float*)d_in[0];
    const float* w1 = (const float*)d_in[1];
    const float* w2 = (const float*)d_in[2];
    const float* w3 = (const float*)d_in[3];
    float* out = (float*)d_out;

    // 24 (n*c) * 8 (w tiles) * 8 (h chunks) = 1536 blocks
    sepconv3d_fused<<<NN * CC * (WW / WT) * (HH / HC), 256>>>(x, w1, w2, w3, out);
}

// round 17
// speedup vs baseline: 1.3812x; 1.0100x over previous
#include <cuda_runtime.h>
#include <cstdint>

// SeparableConv3D: x[8,3,32,256,256] fp32, depthwise K=5 cross-correlation
// along W, then H, then T, zero 'same' padding each stage.
//
// R16 cp.async-ring pipeline + packed f32x2 math (FFMA2) for H- and T-conv:
//   phase A: cp.async rows for iter ii+2 into xbuf[(ii+2)%3], wait_group 1
//            before the barrier (group from a full iteration ago)
//   phase B (lane=t, wg=w-quad): W-conv scalar (4 aligned LDS.64, 40 FFMA),
//            H-conv PACKED (ring of u64 w-pairs, 20 FFMA2), staging stored
//            pair-major sbufP[p=w/2][t][2] via 4x STS.64 (no unpacking)
//   phase C (all 256 threads; thread=(row, pair, t-quad)): T-conv PACKED:
//            4x LDS.128 -> 8 u64 t-pairs, 20 FFMA2, 4x STG.64 (no unpacking)
//   ONE __syncthreads per 2 h-rows; unroll 6 keeps %2/%3 indices static.

#define NN 8
#define CC 3
#define TT 32
#define HH 256
#define WW 256
#define KK 5

#define WT 32                 // w outputs per block
#define HC 32                 // h rows per block -> grid = 24*8*8 = 1536
#define NIT ((HC + 4) / 2)    // 18 iterations of 2 rows
#define XSTRIDE 44            // x slab row stride (conflict-free)
#define RB (TT * XSTRIDE * 4) // bytes per x row-buffer = 5632
#define PSTR 68               // sbufP per-pair stride (floats), R11-verified

typedef unsigned long long u64;

__device__ __forceinline__ void cp16(uint32_t dst, const float* src, bool pred) {
    int sz = pred ? 16 : 0;   // src-size 0 -> 16B zero-fill (pad rows)
    asm volatile("cp.async.cg.shared.global [%0], [%1], 16, %2;\n"
                 :: "r"(dst), "l"(src), "r"(sz));
}
__device__ __forceinline__ void cp_commit() {
    asm volatile("cp.async.commit_group;\n" ::: "memory");
}
__device__ __forceinline__ void cp_wait0() {
    asm volatile("cp.async.wait_group 0;\n" ::: "memory");
}
__device__ __forceinline__ void cp_wait1() {
    asm volatile("cp.async.wait_group 1;\n" ::: "memory");
}

// packed f32x2 helpers
__device__ __forceinline__ u64 pk2(float lo, float hi) {
    u64 r; asm("mov.b64 %0, {%1, %2};" : "=l"(r) : "f"(lo), "f"(hi)); return r;
}
__device__ __forceinline__ u64 fma2(u64 a, u64 b, u64 c) {
    u64 d; asm("fma.rn.f32x2 %0, %1, %2, %3;" : "=l"(d) : "l"(a), "l"(b), "l"(c)); return d;
}
__device__ __forceinline__ u64 mul2(u64 a, u64 b) {
    u64 d; asm("mul.rn.f32x2 %0, %1, %2;" : "=l"(d) : "l"(a), "l"(b)); return d;
}

__global__ void __launch_bounds__(256, 4)
sepconv3d_fused(const float* __restrict__ x,
                const float* __restrict__ w1,   // along W
                const float* __restrict__ w2,   // along H
                const float* __restrict__ w3,   // along T
                float* __restrict__ out)
{
    __shared__ float xbuf[3][2][TT * XSTRIDE];   // [buf][row] cp.async ring
    __shared__ float sbufP[2][2][16 * PSTR];     // [buf][row][pair][t][2]

    const int tid  = threadIdx.x;
    const int lane = tid & 31;     // phase B: = t
    const int wg   = tid >> 5;     // phase B: w-quad

    const int bid = blockIdx.x;               // 0..1535
    const int nc  = bid >> 6;                  // n*3+c
    const int rem = bid & 63;
    const int wt  = rem >> 3;                   // 0..7
    const int hcb = rem & 7;                    // 0..7
    const int c   = nc % CC;

    const int w0 = wt * WT;
    const int h0 = hcb * HC;
    const size_t HW = (size_t)HH * WW;

    const float wW0 = w1[c*KK+0], wW1 = w1[c*KK+1], wW2 = w1[c*KK+2], wW3 = w1[c*KK+3], wW4 = w1[c*KK+4];
    // packed (dup) weights for H and T convs
    const u64 wH0d = pk2(w2[c*KK+0], w2[c*KK+0]);
    const u64 wH1d = pk2(w2[c*KK+1], w2[c*KK+1]);
    const u64 wH2d = pk2(w2[c*KK+2], w2[c*KK+2]);
    const u64 wH3d = pk2(w2[c*KK+3], w2[c*KK+3]);
    const u64 wH4d = pk2(w2[c*KK+4], w2[c*KK+4]);
    const u64 wT0d = pk2(w3[c*KK+0], w3[c*KK+0]);
    const u64 wT1d = pk2(w3[c*KK+1], w3[c*KK+1]);
    const u64 wT2d = pk2(w3[c*KK+2], w3[c*KK+2]);
    const u64 wT3d = pk2(w3[c*KK+3], w3[c*KK+3]);
    const u64 wT4d = pk2(w3[c*KK+4], w3[c*KK+4]);

    const float* xb = x   + (size_t)nc * (TT * HW);
    float*       ob = out + (size_t)nc * (TT * HW);

    // ---- slab-load geometry: item A = tid (all), item B = threads 0-63 ----
    const int trA = tid / 10,  qA = tid - trA * 10;
    const bool hasB = (tid < 64);
    const int iB  = 256 + tid;
    const int trB = iB / 10,   qB = iB - trB * 10;
    const int gwA = w0 - 4 + 4 * qA;
    const int gwB = w0 - 4 + 4 * qB;
    const bool wvA = (gwA >= 0) && (gwA < WW);
    const bool wvB = hasB && (gwB >= 0) && (gwB < WW);
    const float* gA = xb + (size_t)trA * HW + (wvA ? gwA : 0);   // + h*WW
    const float* gB = xb + (size_t)trB * HW + (wvB ? gwB : 0);

    // cp.async destination base addresses
    const uint32_t xbase = (uint32_t)__cvta_generic_to_shared(&xbuf[0][0][0]);
    const uint32_t dA = xbase + (uint32_t)(trA * XSTRIDE + 4 * qA) * 4u;
    const uint32_t dB = xbase + (uint32_t)(trB * XSTRIDE + 4 * qB) * 4u;

    // ---- phase C geometry (R11): thread = (row rr, pair p, t-quad tq) ----
    const int rr  = tid >> 7;          // 0/1
    const int idx = tid & 127;
    const int p   = idx & 15;          // w pair: w = w0 + 2p, 2p+1
    const int tq  = idx >> 4;          // 0..7
    const int t0  = 4 * tq;
    const int pbase = p * PSTR;
    const int q0off = pbase + max(2 * t0 - 4, 0);        // pairs t0-2, t0-1
    const int q1off = pbase + 2 * t0;                    // pairs t0,   t0+1
    const int q2off = pbase + 2 * t0 + 4;                // pairs t0+2, t0+3
    const int q3off = pbase + min(2 * t0 + 8, 2*TT - 8); // pairs t0+4, t0+5
    const bool tlo = (tq == 0);
    const bool thi = (tq == 7);
    // op advances 2 rows per iter; at iter ii it points at row h0 + 2ii - 6 + rr
    float* op = ob + (size_t)t0 * HW + w0 + 2 * p
                   + (size_t)(h0 + rr) * WW - 6 * WW;

    // H-conv register ring as u64 w-pairs: gNl = (s of w 4wg,4wg+1), gNh = (4wg+2,4wg+3)
    u64 g1l = 0, g1h = 0, g2l = 0, g2h = 0, g3l = 0, g3h = 0, g4l = 0, g4h = 0;
    const int scolbase = 4 * wg;
    // phase-B store bases (pair-major): pair 2wg at +0, pair 2wg+1 at +PSTR
    float* const sbP00 = &sbufP[0][0][(2 * wg) * PSTR + 2 * lane];
    float* const sbP01 = &sbufP[0][1][(2 * wg) * PSTR + 2 * lane];
    float* const sbP10 = &sbufP[1][0][(2 * wg) * PSTR + 2 * lane];
    float* const sbP11 = &sbufP[1][1][(2 * wg) * PSTR + 2 * lane];

    // ---- prologue: buf0 <- rows h0-2,h0-1 ; buf1 <- rows h0,h0+1 ----
    {
        int h = h0 - 2;
        bool pA = wvA && (h >= 0);
        cp16(dA + 0u * RB, gA + (size_t)(pA ? h : 0) * WW, pA);
        if (hasB) { bool pB = wvB && (h >= 0);
                    cp16(dB + 0u * RB, gB + (size_t)(pB ? h : 0) * WW, pB); }
        h = h0 - 1;
        pA = wvA && (h >= 0);
        cp16(dA + 1u * RB, gA + (size_t)(pA ? h : 0) * WW, pA);
        if (hasB) { bool pB = wvB && (h >= 0);
                    cp16(dB + 1u * RB, gB + (size_t)(pB ? h : 0) * WW, pB); }
        cp_commit();
        cp16(dA + 2u * RB, gA + (size_t)h0 * WW, wvA);
        cp16(dA + 3u * RB, gA + (size_t)(h0 + 1) * WW, wvA);
        if (hasB) {
            cp16(dB + 2u * RB, gB + (size_t)h0 * WW, wvB);
            cp16(dB + 3u * RB, gB + (size_t)(h0 + 1) * WW, wvB);
        }
        cp_commit();
        cp_wait0();
    }
    __syncthreads();

    // packed T-conv: 4 LDS.128 -> 8 u64 t-pairs m0..m7; 4 output pairs
#define PHASE_C4(SRC)                                                          \
    {                                                                          \
        const float* sp = sbufP[SRC][rr];                                      \
        ulonglong2 Q0 = *reinterpret_cast<const ulonglong2*>(sp + q0off);      \
        ulonglong2 Q1 = *reinterpret_cast<const ulonglong2*>(sp + q1off);      \
        ulonglong2 Q2 = *reinterpret_cast<const ulonglong2*>(sp + q2off);      \
        ulonglong2 Q3 = *reinterpret_cast<const ulonglong2*>(sp + q3off);      \
        u64 m0 = tlo ? 0ULL : Q0.x;   /* s pair at t0-2 (zero-pad t<0)  */     \
        u64 m1 = tlo ? 0ULL : Q0.y;   /* t0-1                            */    \
        u64 m6 = thi ? 0ULL : Q3.x;   /* t0+4 (zero-pad t>31)            */    \
        u64 m7 = thi ? 0ULL : Q3.y;   /* t0+5                            */    \
        u64 o0 = mul2(wT0d, m0);                                               \
        o0 = fma2(wT1d, m1,   o0);                                             \
        o0 = fma2(wT2d, Q1.x, o0);                                             \
        o0 = fma2(wT3d, Q1.y, o0);                                             \
        o0 = fma2(wT4d, Q2.x, o0);                                             \
        u64 o1 = mul2(wT0d, m1);                                               \
        o1 = fma2(wT1d, Q1.x, o1);                                             \
        o1 = fma2(wT2d, Q1.y, o1);                                             \
        o1 = fma2(wT3d, Q2.x, o1);                                             \
        o1 = fma2(wT4d, Q2.y, o1);                                             \
        u64 o2 = mul2(wT0d, Q1.x);                                             \
        o2 = fma2(wT1d, Q1.y, o2);                                             \
        o2 = fma2(wT2d, Q2.x, o2);                                             \
        o2 = fma2(wT3d, Q2.y, o2);                                             \
        o2 = fma2(wT4d, m6,   o2);                                             \
        u64 o3 = mul2(wT0d, Q1.y);                                             \
        o3 = fma2(wT1d, Q2.x, o3);                                             \
        o3 = fma2(wT2d, Q2.y, o3);                                             \
        o3 = fma2(wT3d, m6,   o3);                                             \
        o3 = fma2(wT4d, m7,   o3);                                             \
        *reinterpret_cast<u64*>(op)              = o0;                         \
        *reinterpret_cast<u64*>(op + 1 * HW)     = o1;                         \
        *reinterpret_cast<u64*>(op + 2 * HW)     = o2;                         \
        *reinterpret_cast<u64*>(op + 3 * HW)     = o3;                         \
    }

    #pragma unroll 6
    for (int ii = 0; ii < NIT; ++ii) {
        const int cur3 = ii % 3;         // x ring buffer to read (static)
        const int cur2 = ii & 1;         // sbufP buffer to write (static)

        // ---- 1. issue cp.async group for iteration ii+2 into buf (ii+2)%3 ----
        {
            const int jd = (ii + 2) % 3;
            const int ha = h0 + 2 * ii + 2;
            const int hb = ha + 1;
            const bool live = (ii < NIT - 2);
            bool va = live && wvA && (ha < HH);
            bool vb = live && wvA && (hb < HH);
            cp16(dA + (uint32_t)(2 * jd + 0) * RB, gA + (size_t)(va ? ha : 0) * WW, va);
            cp16(dA + (uint32_t)(2 * jd + 1) * RB, gA + (size_t)(vb ? hb : 0) * WW, vb);
            if (hasB) {
                bool ua = live && wvB && (ha < HH);
                bool ub = live && wvB && (hb < HH);
                cp16(dB + (uint32_t)(2 * jd + 0) * RB, gB + (size_t)(ua ? ha : 0) * WW, ua);
                cp16(dB + (uint32_t)(2 * jd + 1) * RB, gB + (size_t)(ub ? hb : 0) * WW, ub);
            }
            cp_commit();
        }

        // ---- 2. phase B: W-conv scalar, H-conv packed -> sbufP[cur2] ----
        u64 ral, rah, rbl, rbh;
        {
            const float* row0 = &xbuf[cur3][0][lane * XSTRIDE + scolbase + 2];
            float2 a0 = *reinterpret_cast<const float2*>(row0);       // x[w-2,w-1]
            float2 a1 = *reinterpret_cast<const float2*>(row0 + 2);   // x[w  ,w+1]
            float2 a2 = *reinterpret_cast<const float2*>(row0 + 4);   // x[w+2,w+3]
            float2 a3 = *reinterpret_cast<const float2*>(row0 + 6);   // x[w+4,w+5]
            float rx = wW0*a0.x + wW1*a0.y + wW2*a1.x + wW3*a1.y + wW4*a2.x;
            float ry = wW0*a0.y + wW1*a1.x + wW2*a1.y + wW3*a2.x + wW4*a2.y;
            float rz = wW0*a1.x + wW1*a1.y + wW2*a2.x + wW3*a2.y + wW4*a3.x;
            float rw = wW0*a1.y + wW1*a2.x + wW2*a2.y + wW3*a3.x + wW4*a3.y;
            ral = pk2(rx, ry);
            rah = pk2(rz, rw);

            const float* row1 = &xbuf[cur3][1][lane * XSTRIDE + scolbase + 2];
            float2 b0 = *reinterpret_cast<const float2*>(row1);
            float2 b1 = *reinterpret_cast<const float2*>(row1 + 2);
            float2 b2 = *reinterpret_cast<const float2*>(row1 + 4);
            float2 b3 = *reinterpret_cast<const float2*>(row1 + 6);
            float sx = wW0*b0.x + wW1*b0.y + wW2*b1.x + wW3*b1.y + wW4*b2.x;
            float sy = wW0*b0.y + wW1*b1.x + wW2*b1.y + wW3*b2.x + wW4*b2.y;
            float sz = wW0*b1.x + wW1*b1.y + wW2*b2.x + wW3*b2.y + wW4*b3.x;
            float sw = wW0*b1.y + wW1*b2.x + wW2*b2.y + wW3*b3.x + wW4*b3.y;
            rbl = pk2(sx, sy);
            rbh = pk2(sz, sw);
        }

        if (ii >= 2) {
            float* sa = cur2 ? sbP10 : sbP00;   // row a
            float* sb = cur2 ? sbP11 : sbP01;   // row b
            // row a: s = wH0*g1 + wH1*g2 + wH2*g3 + wH3*g4 + wH4*r_a (packed)
            u64 sal = mul2(wH0d, g1l);
            sal = fma2(wH1d, g2l, sal);
            sal = fma2(wH2d, g3l, sal);
            sal = fma2(wH3d, g4l, sal);
            sal = fma2(wH4d, ral, sal);
            u64 sah = mul2(wH0d, g1h);
            sah = fma2(wH1d, g2h, sah);
            sah = fma2(wH2d, g3h, sah);
            sah = fma2(wH3d, g4h, sah);
            sah = fma2(wH4d, rah, sah);
            *reinterpret_cast<u64*>(sa)        = sal;   // pair 2wg
            *reinterpret_cast<u64*>(sa + PSTR) = sah;   // pair 2wg+1
            // row b: s = wH0*g2 + wH1*g3 + wH2*g4 + wH3*r_a + wH4*r_b
            u64 sbl = mul2(wH0d, g2l);
            sbl = fma2(wH1d, g3l, sbl);
            sbl = fma2(wH2d, g4l, sbl);
            sbl = fma2(wH3d, ral, sbl);
            sbl = fma2(wH4d, rbl, sbl);
            u64 sbh = mul2(wH0d, g2h);
            sbh = fma2(wH1d, g3h, sbh);
            sbh = fma2(wH2d, g4h, sbh);
            sbh = fma2(wH3d, rah, sbh);
            sbh = fma2(wH4d, rbh, sbh);
            *reinterpret_cast<u64*>(sb)        = sbl;
            *reinterpret_cast<u64*>(sb + PSTR) = sbh;
        }
        // ring shift by 2 (rename)
        g1l = g3l; g1h = g3h; g2l = g4l; g2h = g4h;
        g3l = ral; g3h = rah; g4l = rbl; g4h = rbh;

        // ---- 3. phase C: packed T-conv from PREVIOUS sbufP; 4t x 2w ----
        if (ii >= 3) {
            PHASE_C4(cur2 ^ 1)
        }
        op += 2 * WW;

        // ---- 4. wait for the group issued ONE iteration ago, then barrier ----
        cp_wait1();
        __syncthreads();
        // wait_group 1: group issued at iter ii-1 (data for iter ii+1) is done.
        // barrier orders: sbufP[cur2] writes vs next-iter phase-C reads;
        // phase-C reads of sbufP[cur2^1] vs its rewrite at iter ii+1;
        // cp.async-completed xbuf data vs all threads' next-iter LDS.
    }

    // ---- epilogue: last 2 output rows from sbufP[(NIT-1)&1] ----
    // op has advanced 2*NIT rows: points at row h0 + 30 + rr
    PHASE_C4((NIT - 1) & 1)

#undef PHASE_C4
}

extern "C" void kernel_launch(void* const* d_in, const int* in_sizes, int n_in,
                              void* d_out, int out_size)
{
    const float* x  = (const float*)d_in[0];
    const float* w1 = (const float*)d_in[1];
    const float* w2 = (const float*)d_in[2];
    const float* w3 = (const float*)d_in[3];
    float* out = (float*)d_out;

    // 24 (n*c) * 8 (w tiles) * 8 (h chunks) = 1536 blocks
    sepconv3d_fused<<<NN * CC * (WW / WT) * (HH / HC), 256>>>(x, w1, w2, w3, out);
}